// round 16
// baseline (speedup 1.0000x reference)
#include <cuda_runtime.h>
#include <cuda_bf16.h>

#define N_NODES   100000
#define N_EDGES   1600000
#define FEAT      64
#define N_GRAPHS  256
#define N_CLASSES 45

#define SCAN_BLK  1024
#define SCAN_NBLK ((N_NODES + SCAN_BLK - 1) / SCAN_BLK)   // 98

// ---- scratch (static; no allocations allowed) ----
__device__ unsigned g_hb[N_NODES * 32];    // bf16x2(h * dinv), 32 pairs per node
__device__ float g_act[N_NODES * FEAT];    // layer output (fp32), layers 1-2
__device__ float g_dinv[N_NODES];
__device__ int   g_deg[N_NODES];
__device__ int   g_scan[N_NODES];
__device__ int   g_bsum[SCAN_NBLK];
__device__ int   g_off[N_NODES + 1];
__device__ int   g_cursor[N_NODES];
__device__ int   g_esrc[N_EDGES];
__device__ float g_pool[N_GRAPHS * FEAT];
__device__ float g_cnt[N_GRAPHS];

// ================================================================ CSR build
__global__ void k_zero() {
    int i = blockIdx.x * blockDim.x + threadIdx.x;
    if (i < N_NODES) g_deg[i] = 0;
    if (i < N_GRAPHS * FEAT) g_pool[i] = 0.0f;
    if (i < N_GRAPHS) g_cnt[i] = 0.0f;
}

__global__ void k_hist(const int* __restrict__ dst) {
    int e = blockIdx.x * blockDim.x + threadIdx.x;
    if (e < N_EDGES) atomicAdd(&g_deg[dst[e]], 1);
}

// shuffle-based inclusive scan over 1024-element chunks (2 barriers);
// also accumulates per-graph node counts (pool denominator).
__global__ void k_scanA(const int* __restrict__ batch) {
    int t = threadIdx.x;
    int lane = t & 31;
    int w = t >> 5;
    int idx = blockIdx.x * SCAN_BLK + t;
    int orig = (idx < N_NODES) ? g_deg[idx] : 0;

    if (idx < N_NODES) atomicAdd(&g_cnt[batch[idx]], 1.0f);

    int v = orig;
#pragma unroll
    for (int o = 1; o < 32; o <<= 1) {
        int x = __shfl_up_sync(0xffffffffu, v, o);
        if (lane >= o) v += x;
    }

    __shared__ int wsum[32];
    if (lane == 31) wsum[w] = v;
    __syncthreads();

    if (w == 0) {
        int s = wsum[lane];
        int e = s;
#pragma unroll
        for (int o = 1; o < 32; o <<= 1) {
            int x = __shfl_up_sync(0xffffffffu, e, o);
            if (lane >= o) e += x;
        }
        wsum[lane] = e - s;
    }
    __syncthreads();

    int incl = v + wsum[w];
    if (idx < N_NODES) g_scan[idx] = incl;
    if (t == SCAN_BLK - 1) g_bsum[blockIdx.x] = incl;
}

// scanC with fused cross-chunk prefix
__global__ void k_scanC() {
    int t = threadIdx.x;
    int idx = blockIdx.x * blockDim.x + t;
    int chunk = (blockIdx.x * blockDim.x) / SCAN_BLK;

    int part = (t < chunk) ? g_bsum[t] : 0;
#pragma unroll
    for (int o = 16; o; o >>= 1) part += __shfl_down_sync(0xffffffffu, part, o);
    __shared__ int sred[8];
    if ((t & 31) == 0) sred[t >> 5] = part;
    __syncthreads();
    __shared__ int prefix;
    if (t < 8) {
        int v = sred[t];
#pragma unroll
        for (int o = 4; o; o >>= 1) v += __shfl_down_sync(0xffu, v, o);
        if (t == 0) prefix = v;
    }
    __syncthreads();

    if (idx < N_NODES) {
        int deg = g_deg[idx];
        int incl = g_scan[idx] + prefix;
        g_off[idx] = incl - deg;
        g_dinv[idx] = rsqrtf((float)deg + 1.0f);
        g_cursor[idx] = 0;
    }
    if (idx == 0) g_off[N_NODES] = N_EDGES;
}

__global__ void k_fill(const int* __restrict__ src, const int* __restrict__ dst) {
    int e = blockIdx.x * blockDim.x + threadIdx.x;
    if (e >= N_EDGES) return;
    int d = dst[e];
    int pos = g_off[d] + atomicAdd(&g_cursor[d], 1);
    g_esrc[pos] = src[e];
}

// ================================================================ GEMM h = in @ W (64x64) — R11 proven FFMA
__global__ void k_gemm(const float* __restrict__ in, const float* __restrict__ W,
                       int relu_in) {
    __shared__ float Ws[64 * 64];
    __shared__ float Xs[64 * 64];
    int tid = threadIdx.x;
    int row0 = blockIdx.x * 64;

#pragma unroll
    for (int i = 0; i < 16; i++) Ws[tid + i * 256] = W[tid + i * 256];

#pragma unroll
    for (int i = 0; i < 16; i++) {
        int lin = tid + i * 256;
        int r = lin >> 6;
        int gr = row0 + r;
        float v = 0.0f;
        if (gr < N_NODES) v = in[gr * 64 + (lin & 63)];
        if (relu_in) v = fmaxf(v, 0.0f);
        Xs[lin] = v;
    }
    __syncthreads();

    int tx = tid & 15;
    int ty = tid >> 4;
    float acc[4][4] = {};

#pragma unroll
    for (int k = 0; k < 64; k += 4) {
        float4 xv[4];
#pragma unroll
        for (int j = 0; j < 4; j++)
            xv[j] = *(const float4*)&Xs[(ty * 4 + j) * 64 + k];
#pragma unroll
        for (int kk = 0; kk < 4; kk++) {
            float w0 = Ws[(k + kk) * 64 + 2 * tx];
            float w1 = Ws[(k + kk) * 64 + 2 * tx + 1];
            float w2 = Ws[(k + kk) * 64 + 2 * tx + 32];
            float w3 = Ws[(k + kk) * 64 + 2 * tx + 33];
#pragma unroll
            for (int j = 0; j < 4; j++) {
                float x = (&xv[j].x)[kk];
                acc[j][0] += x * w0;
                acc[j][1] += x * w1;
                acc[j][2] += x * w2;
                acc[j][3] += x * w3;
            }
        }
    }

#pragma unroll
    for (int j = 0; j < 4; j++) {
        int gr = row0 + ty * 4 + j;
        if (gr < N_NODES) {
            float d = g_dinv[gr];
            __nv_bfloat162 p0 = __floats2bfloat162_rn(acc[j][0] * d, acc[j][1] * d);
            __nv_bfloat162 p1 = __floats2bfloat162_rn(acc[j][2] * d, acc[j][3] * d);
            g_hb[gr * 32 + tx]      = *(unsigned*)&p0;
            g_hb[gr * 32 + tx + 16] = *(unsigned*)&p1;
        }
    }
}

// ================================================================ pull aggregation: warp per node (R11 proven)
__device__ __forceinline__ void agg_edge(float2& acc, unsigned v) {
    acc.x += __uint_as_float(v << 16);
    acc.y += __uint_as_float(v & 0xffff0000u);
}

__device__ __forceinline__ float2 warp_agg(int node, int lane) {
    unsigned own = g_hb[node * 32 + lane];
    float2 acc;
    acc.x = __uint_as_float(own << 16);
    acc.y = __uint_as_float(own & 0xffff0000u);

    int j = g_off[node];
    int j1 = g_off[node + 1];

    while (j < j1) {
        int rem = j1 - j;
        int n = rem < 32 ? rem : 32;
        int s = (lane < n) ? __ldg(&g_esrc[j + lane]) : 0;

        int k = 0;
        for (; k + 4 <= n; k += 4) {
            int s0 = __shfl_sync(0xffffffffu, s, k);
            int s1 = __shfl_sync(0xffffffffu, s, k + 1);
            int s2 = __shfl_sync(0xffffffffu, s, k + 2);
            int s3 = __shfl_sync(0xffffffffu, s, k + 3);
            unsigned v0 = __ldg(&g_hb[s0 * 32 + lane]);
            unsigned v1 = __ldg(&g_hb[s1 * 32 + lane]);
            unsigned v2 = __ldg(&g_hb[s2 * 32 + lane]);
            unsigned v3 = __ldg(&g_hb[s3 * 32 + lane]);
            agg_edge(acc, v0);
            agg_edge(acc, v1);
            agg_edge(acc, v2);
            agg_edge(acc, v3);
        }
        for (; k < n; k++) {
            int sk = __shfl_sync(0xffffffffu, s, k);
            agg_edge(acc, __ldg(&g_hb[sk * 32 + lane]));
        }
        j += n;
    }
    return acc;
}

// layers 1,2: write act
__global__ void k_agg(const float* __restrict__ b, float* __restrict__ out) {
    int node = blockIdx.x * 8 + (threadIdx.x >> 5);
    int lane = threadIdx.x & 31;
    if (node >= N_NODES) return;

    float2 acc = warp_agg(node, lane);
    float d = g_dinv[node];
    float2 r;
    r.x = acc.x * d + b[2 * lane];
    r.y = acc.y * d + b[2 * lane + 1];
    *(float2*)&out[node * 64 + 2 * lane] = r;
}

// layer 3: reduce straight into the pooling accumulator (no act round-trip)
__global__ void k_agg_pool(const float* __restrict__ b, const int* __restrict__ batch) {
    int node = blockIdx.x * 8 + (threadIdx.x >> 5);
    int lane = threadIdx.x & 31;
    if (node >= N_NODES) return;

    float2 acc = warp_agg(node, lane);
    float d = g_dinv[node];
    float rx = acc.x * d + b[2 * lane];
    float ry = acc.y * d + b[2 * lane + 1];

    int g = __ldg(&batch[node]);
    float* p = &g_pool[g * 64 + 2 * lane];
    asm volatile("red.global.add.v2.f32 [%0], {%1, %2};"
                 :: "l"(p), "f"(rx), "f"(ry) : "memory");
}

// ================================================================ head
__global__ void k_final(const float* __restrict__ Wl, const float* __restrict__ bl,
                        float* __restrict__ out) {
    int g = blockIdx.x;
    int tid = threadIdx.x;  // 64
    __shared__ float p[64];
    float inv = 1.0f / fmaxf(g_cnt[g], 1.0f);
    p[tid] = g_pool[g * 64 + tid] * inv;
    __syncthreads();
    if (tid < N_CLASSES) {
        float acc = bl[tid];
#pragma unroll
        for (int k = 0; k < 64; k++) acc += p[k] * Wl[k * N_CLASSES + tid];
        out[g * N_CLASSES + tid] = acc;
    }
}

// ================================================================ launch
extern "C" void kernel_launch(void* const* d_in, const int* in_sizes, int n_in,
                              void* d_out, int out_size) {
    const float* x     = (const float*)d_in[0];
    const int*   ei    = (const int*)d_in[1];
    const int*   batch = (const int*)d_in[2];
    const float* W1    = (const float*)d_in[3];
    const float* b1    = (const float*)d_in[4];
    const float* W2    = (const float*)d_in[5];
    const float* b2    = (const float*)d_in[6];
    const float* W3    = (const float*)d_in[7];
    const float* b3    = (const float*)d_in[8];
    const float* Wl    = (const float*)d_in[9];
    const float* bl    = (const float*)d_in[10];
    const int* src = ei;
    const int* dst = ei + N_EDGES;

    float* act;
    cudaGetSymbolAddress((void**)&act, g_act);

    const int TPB = 256;
    int grid_n    = (N_NODES + TPB - 1) / TPB;
    int grid_e    = (N_EDGES + TPB - 1) / TPB;
    int grid_gemm = (N_NODES + 63) / 64;
    int grid_agg  = (N_NODES + 7) / 8;

    // ---- CSR build (once, reused by all 3 layers) ----
    k_zero<<<grid_n, TPB>>>();
    k_hist<<<grid_e, TPB>>>(dst);
    k_scanA<<<SCAN_NBLK, SCAN_BLK>>>(batch);
    k_scanC<<<grid_n, TPB>>>();
    k_fill<<<grid_e, TPB>>>(src, dst);

    // ---- layer 1 ----
    k_gemm<<<grid_gemm, TPB>>>(x, W1, 0);
    k_agg<<<grid_agg, 256>>>(b1, act);

    // ---- layer 2 ----
    k_gemm<<<grid_gemm, TPB>>>(act, W2, 1);
    k_agg<<<grid_agg, 256>>>(b2, act);

    // ---- layer 3 (agg fused into pooling) ----
    k_gemm<<<grid_gemm, TPB>>>(act, W3, 1);
    k_agg_pool<<<grid_agg, 256>>>(b3, batch);

    // ---- head ----
    k_final<<<N_GRAPHS, 64>>>(Wl, bl, (float*)d_out);
}

// round 17
// speedup vs baseline: 1.1681x; 1.1681x over previous
#include <cuda_runtime.h>
#include <cuda_bf16.h>

#define N_NODES   100000
#define N_EDGES   1600000
#define FEAT      64
#define N_GRAPHS  256
#define N_CLASSES 45

#define SCAN_BLK  1024
#define SCAN_NBLK ((N_NODES + SCAN_BLK - 1) / SCAN_BLK)   // 98
#define GEMM_BLKS ((N_NODES + 63) / 64)                   // 1563
#define EDGES_PER_BLK 1024                                // 1563*1024 >= N_EDGES

// ---- scratch (static; no allocations allowed) ----
__device__ unsigned g_hb[N_NODES * 32];    // bf16x2(h * dinv), 32 pairs per node
__device__ float g_act[N_NODES * FEAT];    // layer output (fp32)
__device__ float g_dinv[N_NODES];
__device__ int   g_deg[N_NODES];
__device__ int   g_scan[N_NODES];
__device__ int   g_bsum[SCAN_NBLK];
__device__ int   g_off[N_NODES + 1];
__device__ int   g_cursor[N_NODES];
__device__ int   g_esrc[N_EDGES];
__device__ float g_pool[N_GRAPHS * FEAT];
__device__ float g_cnt[N_GRAPHS];

// ================================================================ CSR build
__global__ void k_zero() {
    int i = blockIdx.x * blockDim.x + threadIdx.x;
    if (i < N_NODES) g_deg[i] = 0;
    if (i < N_GRAPHS * FEAT) g_pool[i] = 0.0f;
    if (i < N_GRAPHS) g_cnt[i] = 0.0f;
}

__global__ void k_hist(const int* __restrict__ dst) {
    int e = blockIdx.x * blockDim.x + threadIdx.x;
    if (e < N_EDGES) atomicAdd(&g_deg[dst[e]], 1);
}

// shuffle-based inclusive scan over 1024-element chunks (2 barriers total)
__global__ void k_scanA() {
    int t = threadIdx.x;
    int lane = t & 31;
    int w = t >> 5;                 // 0..31
    int idx = blockIdx.x * SCAN_BLK + t;
    int orig = (idx < N_NODES) ? g_deg[idx] : 0;

    int v = orig;
#pragma unroll
    for (int o = 1; o < 32; o <<= 1) {
        int x = __shfl_up_sync(0xffffffffu, v, o);
        if (lane >= o) v += x;
    }

    __shared__ int wsum[32];
    if (lane == 31) wsum[w] = v;
    __syncthreads();

    if (w == 0) {
        int s = wsum[lane];
        int e = s;
#pragma unroll
        for (int o = 1; o < 32; o <<= 1) {
            int x = __shfl_up_sync(0xffffffffu, e, o);
            if (lane >= o) e += x;
        }
        wsum[lane] = e - s;
    }
    __syncthreads();

    int incl = v + wsum[w];
    if (idx < N_NODES) g_scan[idx] = incl;
    if (t == SCAN_BLK - 1) g_bsum[blockIdx.x] = incl;
}

// scanC with fused cross-chunk prefix (each block reduces g_bsum[0..chunk-1])
__global__ void k_scanC() {
    int t = threadIdx.x;
    int idx = blockIdx.x * blockDim.x + t;
    int chunk = (blockIdx.x * blockDim.x) / SCAN_BLK;

    int part = (t < chunk) ? g_bsum[t] : 0;
#pragma unroll
    for (int o = 16; o; o >>= 1) part += __shfl_down_sync(0xffffffffu, part, o);
    __shared__ int sred[8];
    if ((t & 31) == 0) sred[t >> 5] = part;
    __syncthreads();
    __shared__ int prefix;
    if (t < 8) {
        int v = sred[t];
#pragma unroll
        for (int o = 4; o; o >>= 1) v += __shfl_down_sync(0xffu, v, o);
        if (t == 0) prefix = v;
    }
    __syncthreads();

    if (idx < N_NODES) {
        int deg = g_deg[idx];
        int incl = g_scan[idx] + prefix;
        g_off[idx] = incl - deg;
        g_dinv[idx] = rsqrtf((float)deg + 1.0f);
        g_cursor[idx] = 0;
    }
    if (idx == 0) g_off[N_NODES] = N_EDGES;
}

// ---------------------------------------------------------------- GEMM body (R11/R14 proven)
__device__ __forceinline__ void gemm_body(const float* __restrict__ in,
                                          const float* __restrict__ W,
                                          int relu_in, int row0) {
    __shared__ float Ws[64 * 64];
    __shared__ float Xs[64 * 64];
    int tid = threadIdx.x;

#pragma unroll
    for (int i = 0; i < 16; i++) Ws[tid + i * 256] = W[tid + i * 256];

#pragma unroll
    for (int i = 0; i < 16; i++) {
        int lin = tid + i * 256;
        int r = lin >> 6;
        int gr = row0 + r;
        float v = 0.0f;
        if (gr < N_NODES) v = in[gr * 64 + (lin & 63)];
        if (relu_in) v = fmaxf(v, 0.0f);
        Xs[lin] = v;
    }
    __syncthreads();

    int tx = tid & 15;
    int ty = tid >> 4;
    float acc[4][4] = {};

#pragma unroll
    for (int k = 0; k < 64; k += 4) {
        float4 xv[4];
#pragma unroll
        for (int j = 0; j < 4; j++)
            xv[j] = *(const float4*)&Xs[(ty * 4 + j) * 64 + k];
#pragma unroll
        for (int kk = 0; kk < 4; kk++) {
            float w0 = Ws[(k + kk) * 64 + 2 * tx];
            float w1 = Ws[(k + kk) * 64 + 2 * tx + 1];
            float w2 = Ws[(k + kk) * 64 + 2 * tx + 32];
            float w3 = Ws[(k + kk) * 64 + 2 * tx + 33];
#pragma unroll
            for (int j = 0; j < 4; j++) {
                float x = (&xv[j].x)[kk];
                acc[j][0] += x * w0;
                acc[j][1] += x * w1;
                acc[j][2] += x * w2;
                acc[j][3] += x * w3;
            }
        }
    }

#pragma unroll
    for (int j = 0; j < 4; j++) {
        int gr = row0 + ty * 4 + j;
        if (gr < N_NODES) {
            float d = g_dinv[gr];
            __nv_bfloat162 p0 = __floats2bfloat162_rn(acc[j][0] * d, acc[j][1] * d);
            __nv_bfloat162 p1 = __floats2bfloat162_rn(acc[j][2] * d, acc[j][3] * d);
            g_hb[gr * 32 + tx]      = *(unsigned*)&p0;
            g_hb[gr * 32 + tx + 16] = *(unsigned*)&p1;
        }
    }
}

// layer-1 GEMM with CSR-fill tail work (same block, after epilogue, no barrier,
// no extra smem -> occupancy identical to plain k_gemm; fill hides under FMA
// work of concurrently resident blocks).
__global__ void k_gemm1_fill(const float* __restrict__ in, const float* __restrict__ W,
                             const int* __restrict__ src, const int* __restrict__ dst) {
    gemm_body(in, W, 0, blockIdx.x * 64);

    int e0 = blockIdx.x * EDGES_PER_BLK;
#pragma unroll
    for (int i = 0; i < EDGES_PER_BLK / 256; i++) {
        int e = e0 + i * 256 + threadIdx.x;
        if (e < N_EDGES) {
            int d = dst[e];
            int pos = g_off[d] + atomicAdd(&g_cursor[d], 1);
            g_esrc[pos] = src[e];
        }
    }
}

// layers 2,3 GEMM
__global__ void k_gemm(const float* __restrict__ in, const float* __restrict__ W,
                       int relu_in) {
    gemm_body(in, W, relu_in, blockIdx.x * 64);
}

// ================================================================ pull aggregation: warp per node (R11 proven)
__device__ __forceinline__ void agg_edge(float2& acc, unsigned v) {
    acc.x += __uint_as_float(v << 16);
    acc.y += __uint_as_float(v & 0xffff0000u);
}

__global__ void k_agg(const float* __restrict__ b, float* __restrict__ out) {
    int node = blockIdx.x * 8 + (threadIdx.x >> 5);
    int lane = threadIdx.x & 31;
    if (node >= N_NODES) return;

    unsigned own = g_hb[node * 32 + lane];
    float2 acc;
    acc.x = __uint_as_float(own << 16);
    acc.y = __uint_as_float(own & 0xffff0000u);

    int j = g_off[node];
    int j1 = g_off[node + 1];

    while (j < j1) {                       // j, j1 warp-uniform
        int rem = j1 - j;
        int n = rem < 32 ? rem : 32;
        int s = (lane < n) ? __ldg(&g_esrc[j + lane]) : 0;

        int k = 0;
        for (; k + 4 <= n; k += 4) {
            int s0 = __shfl_sync(0xffffffffu, s, k);
            int s1 = __shfl_sync(0xffffffffu, s, k + 1);
            int s2 = __shfl_sync(0xffffffffu, s, k + 2);
            int s3 = __shfl_sync(0xffffffffu, s, k + 3);
            unsigned v0 = __ldg(&g_hb[s0 * 32 + lane]);
            unsigned v1 = __ldg(&g_hb[s1 * 32 + lane]);
            unsigned v2 = __ldg(&g_hb[s2 * 32 + lane]);
            unsigned v3 = __ldg(&g_hb[s3 * 32 + lane]);
            agg_edge(acc, v0);
            agg_edge(acc, v1);
            agg_edge(acc, v2);
            agg_edge(acc, v3);
        }
        for (; k < n; k++) {
            int sk = __shfl_sync(0xffffffffu, s, k);
            agg_edge(acc, __ldg(&g_hb[sk * 32 + lane]));
        }
        j += n;
    }

    float d = g_dinv[node];
    float2 r;
    r.x = acc.x * d + b[2 * lane];
    r.y = acc.y * d + b[2 * lane + 1];
    *(float2*)&out[node * 64 + 2 * lane] = r;
}

// ================================================================ pooling (4 interleaved chains / block) — R14 proven
#define POOL_NODES 256
__global__ void k_pool(const float* __restrict__ hin, const int* __restrict__ batch) {
    int f = threadIdx.x & 63;       // feature
    int c = threadIdx.x >> 6;       // chain 0..3
    int base = blockIdx.x * POOL_NODES;
    int n0 = base + c;
    if (n0 >= N_NODES) return;
    int n1 = base + POOL_NODES;
    if (n1 > N_NODES) n1 = N_NODES;

    float acc = 0.0f;
    float cnt = 0.0f;
    int curg = batch[n0];
    for (int n = n0; n < n1; n += 4) {
        int g = batch[n];
        if (g != curg) {
            atomicAdd(&g_pool[curg * 64 + f], acc);
            if (f == 0) atomicAdd(&g_cnt[curg], cnt);
            acc = 0.0f;
            cnt = 0.0f;
            curg = g;
        }
        acc += hin[n * 64 + f];
        cnt += 1.0f;
    }
    atomicAdd(&g_pool[curg * 64 + f], acc);
    if (f == 0) atomicAdd(&g_cnt[curg], cnt);
}

__global__ void k_final(const float* __restrict__ Wl, const float* __restrict__ bl,
                        float* __restrict__ out) {
    int g = blockIdx.x;
    int tid = threadIdx.x;  // 64
    __shared__ float p[64];
    float inv = 1.0f / fmaxf(g_cnt[g], 1.0f);
    p[tid] = g_pool[g * 64 + tid] * inv;
    __syncthreads();
    if (tid < N_CLASSES) {
        float acc = bl[tid];
#pragma unroll
        for (int k = 0; k < 64; k++) acc += p[k] * Wl[k * N_CLASSES + tid];
        out[g * N_CLASSES + tid] = acc;
    }
}

// ================================================================ launch
extern "C" void kernel_launch(void* const* d_in, const int* in_sizes, int n_in,
                              void* d_out, int out_size) {
    const float* x     = (const float*)d_in[0];
    const int*   ei    = (const int*)d_in[1];
    const int*   batch = (const int*)d_in[2];
    const float* W1    = (const float*)d_in[3];
    const float* b1    = (const float*)d_in[4];
    const float* W2    = (const float*)d_in[5];
    const float* b2    = (const float*)d_in[6];
    const float* W3    = (const float*)d_in[7];
    const float* b3    = (const float*)d_in[8];
    const float* Wl    = (const float*)d_in[9];
    const float* bl    = (const float*)d_in[10];
    const int* src = ei;
    const int* dst = ei + N_EDGES;

    float* act;
    cudaGetSymbolAddress((void**)&act, g_act);

    const int TPB = 256;
    int grid_n    = (N_NODES + TPB - 1) / TPB;
    int grid_e    = (N_EDGES + TPB - 1) / TPB;
    int grid_agg  = (N_NODES + 7) / 8;
    int grid_pool = (N_NODES + POOL_NODES - 1) / POOL_NODES;

    // ---- CSR build prefix ----
    k_zero<<<grid_n, TPB>>>();
    k_hist<<<grid_e, TPB>>>(dst);
    k_scanA<<<SCAN_NBLK, SCAN_BLK>>>();
    k_scanC<<<grid_n, TPB>>>();

    // ---- layer 1 GEMM with fill tail (fill hides under gemm FMA work) ----
    k_gemm1_fill<<<GEMM_BLKS, TPB>>>(x, W1, src, dst);
    k_agg<<<grid_agg, 256>>>(b1, act);

    // ---- layer 2 ----
    k_gemm<<<GEMM_BLKS, TPB>>>(act, W2, 1);
    k_agg<<<grid_agg, 256>>>(b2, act);

    // ---- layer 3 ----
    k_gemm<<<GEMM_BLKS, TPB>>>(act, W3, 1);
    k_agg<<<grid_agg, 256>>>(b3, act);

    // ---- mean pool + head ----
    k_pool<<<grid_pool, 256>>>(act, batch);
    k_final<<<N_GRAPHS, 64>>>(Wl, bl, (float*)d_out);
}